// round 4
// baseline (speedup 1.0000x reference)
#include <cuda_runtime.h>
#include <cuda_bf16.h>
#include <cstdint>

// Problem constants
#define B_SZ   8192
#define L_SZ   64
#define EMB    64
#define HID    128
#define G3     384     // 3*HID
#define OUTD   128
#define NVAL   1000

// ---------------- device scratch (no cudaMalloc allowed) ----------------
__device__ float g_tab[NVAL * G3];      // [v][gj] precomputed embed[v]@Wih^T + bias (1.5 MB, L2-hot)
__device__ float g_Wih_t[EMB * G3];     // [k][gj]
__device__ float g_Whh_t[HID * G3];     // [k][gj]
__device__ float g_Wout_t[HID * OUTD];  // [k][o]
__device__ float g_cbias[G3];           // b_ih + (b_hh for r,z only)

// ---------------- helpers ----------------
__device__ __forceinline__ float2 ffma2(float2 a, float2 b, float2 c) {
    unsigned long long au = *reinterpret_cast<unsigned long long*>(&a);
    unsigned long long bu = *reinterpret_cast<unsigned long long*>(&b);
    unsigned long long cu = *reinterpret_cast<unsigned long long*>(&c);
    unsigned long long du;
    asm("fma.rn.f32x2 %0, %1, %2, %3;" : "=l"(du) : "l"(au), "l"(bu), "l"(cu));
    return *reinterpret_cast<float2*>(&du);
}

__device__ __forceinline__ float fsig(float x) {
    float e;
    asm("ex2.approx.f32 %0, %1;" : "=f"(e) : "f"(-1.4426950408889634f * x));
    float r;
    asm("rcp.approx.f32 %0, %1;" : "=f"(r) : "f"(1.0f + e));
    return r;
}

__device__ __forceinline__ float ftanh(float x) {
    float e;
    asm("ex2.approx.f32 %0, %1;" : "=f"(e) : "f"(-2.8853900817779268f * x));
    float r;
    asm("rcp.approx.f32 %0, %1;" : "=f"(r) : "f"(1.0f + e));
    return fmaf(2.0f, r, -1.0f);
}

// ---------------- prep: transposes + combined bias ----------------
__global__ void prep_kernel(const float* __restrict__ Wih,
                            const float* __restrict__ Whh,
                            const float* __restrict__ bih,
                            const float* __restrict__ bhh,
                            const float* __restrict__ Wout) {
    int i = blockIdx.x * blockDim.x + threadIdx.x;
    if (i < EMB * G3) {
        int k = i / G3, gj = i % G3;
        g_Wih_t[i] = Wih[gj * EMB + k];
    }
    if (i < HID * G3) {
        int k = i / G3, gj = i % G3;
        g_Whh_t[i] = Whh[gj * HID + k];
    }
    if (i < HID * OUTD) {
        int k = i / OUTD, o = i % OUTD;
        g_Wout_t[i] = Wout[o * HID + k];
    }
    if (i < G3) {
        g_cbias[i] = bih[i] + (i < 2 * HID ? bhh[i] : 0.0f);
    }
}

// ---------------- table: tab[v][gj] = sum_k embed[v][k] * Wih_t[k][gj] + cbias[gj] ----------------
__global__ void table_kernel(const float* __restrict__ embed) {
    __shared__ float es[EMB];
    const int v = blockIdx.x;
    const int gj = threadIdx.x;
    if (gj < EMB) es[gj] = embed[v * EMB + gj];
    __syncthreads();
    float acc = 0.0f;
    #pragma unroll 8
    for (int k = 0; k < EMB; k++)
        acc = fmaf(es[k], g_Wih_t[k * G3 + gj], acc);
    g_tab[v * G3 + gj] = acc + g_cbias[gj];
}

// ---------------- phase 2: GRU recurrence + output projection ----------------
// grid 128, block 256, dyn smem = Whh_t(192KB) + h(128x65, 33.3KB)
#define HSTRIDE 65
#define P2_SMEM (HID * G3 * 4 + HID * HSTRIDE * 4)
__global__ __launch_bounds__(256, 1) void phase2_kernel(const int* __restrict__ x,
                                                        const float* __restrict__ bhh,
                                                        const float* __restrict__ bout,
                                                        float* __restrict__ out) {
    extern __shared__ float sm2[];
    float* Ws = sm2;                // [k][gj] 128x384
    float* Hs = sm2 + HID * G3;     // [k][b]  128x65

    const int tid = threadIdx.x;
    const int b0 = blockIdx.x * 64;
    const float* __restrict__ tab = g_tab;

    {
        const float4* src = (const float4*)g_Whh_t;
        float4* dst = (float4*)Ws;
        #pragma unroll
        for (int i = tid; i < HID * G3 / 4; i += 256) dst[i] = src[i];
    }
    for (int i = tid; i < HID * HSTRIDE; i += 256) Hs[i] = 0.0f;

    const int tx = tid & 31, ty = tid >> 5;
    float4 pbn4 = *(const float4*)(bhh + 256 + tx * 4);
    float2 pbn0 = make_float2(pbn4.x, pbn4.y);
    float2 pbn1 = make_float2(pbn4.z, pbn4.w);
    __syncthreads();

    const float* wrow = Ws + tx * 4;
    const float* hrow = Hs + ty * 8;

    for (int t = 0; t < L_SZ; t++) {
        // gather token table rows: idx per batch row, xg slices from L2-resident table
        int idx[8];
        #pragma unroll
        for (int b = 0; b < 8; b++)
            idx[b] = x[(size_t)(b0 + ty * 8 + b) * L_SZ + t];

        float2 ar[2][8], az[2][8], an[2][8];
        #pragma unroll
        for (int b = 0; b < 8; b++) {
            const float* trow = tab + (size_t)idx[b] * G3 + tx * 4;
            float4 vr = __ldg((const float4*)(trow));
            float4 vz = __ldg((const float4*)(trow + 128));
            ar[0][b] = make_float2(vr.x, vr.y); ar[1][b] = make_float2(vr.z, vr.w);
            az[0][b] = make_float2(vz.x, vz.y); az[1][b] = make_float2(vz.z, vz.w);
            an[0][b] = pbn0;                    an[1][b] = pbn1;
        }

        #pragma unroll 2
        for (int k = 0; k < HID; k++) {
            float4 wr = *(const float4*)(wrow + k * G3);
            float4 wz = *(const float4*)(wrow + k * G3 + 128);
            float4 wn = *(const float4*)(wrow + k * G3 + 256);
            float2 wr0 = make_float2(wr.x, wr.y), wr1 = make_float2(wr.z, wr.w);
            float2 wz0 = make_float2(wz.x, wz.y), wz1 = make_float2(wz.z, wz.w);
            float2 wn0 = make_float2(wn.x, wn.y), wn1 = make_float2(wn.z, wn.w);
            #pragma unroll
            for (int b = 0; b < 8; b++) {
                float h = hrow[k * HSTRIDE + b];
                float2 h2 = make_float2(h, h);
                ar[0][b] = ffma2(wr0, h2, ar[0][b]);
                ar[1][b] = ffma2(wr1, h2, ar[1][b]);
                az[0][b] = ffma2(wz0, h2, az[0][b]);
                az[1][b] = ffma2(wz1, h2, az[1][b]);
                an[0][b] = ffma2(wn0, h2, an[0][b]);
                an[1][b] = ffma2(wn1, h2, an[1][b]);
            }
        }

        // gate math (reads old h; h writes happen after the barrier)
        float hnew[8][4];
        #pragma unroll
        for (int b = 0; b < 8; b++) {
            float4 xn4 = __ldg((const float4*)(tab + (size_t)idx[b] * G3 + 256 + tx * 4));
            float xn[4] = {xn4.x, xn4.y, xn4.z, xn4.w};
            float rr[4] = {ar[0][b].x, ar[0][b].y, ar[1][b].x, ar[1][b].y};
            float zz[4] = {az[0][b].x, az[0][b].y, az[1][b].x, az[1][b].y};
            float nn[4] = {an[0][b].x, an[0][b].y, an[1][b].x, an[1][b].y};
            #pragma unroll
            for (int j = 0; j < 4; j++) {
                float r = fsig(rr[j]);
                float z = fsig(zz[j]);
                float n = ftanh(fmaf(r, nn[j], xn[j]));
                float hold = Hs[(tx * 4 + j) * HSTRIDE + ty * 8 + b];
                hnew[b][j] = fmaf(z, hold - n, n);   // (1-z)*n + z*h
            }
        }
        __syncthreads();
        #pragma unroll
        for (int b = 0; b < 8; b++)
            #pragma unroll
            for (int j = 0; j < 4; j++)
                Hs[(tx * 4 + j) * HSTRIDE + ty * 8 + b] = hnew[b][j];
        __syncthreads();
    }

    // output projection: out[b][o] = sum_k Hs[k][b] * Wout_t[k][o] + bout[o]
    float2 oa[2][8];
    #pragma unroll
    for (int p = 0; p < 2; p++)
        #pragma unroll
        for (int b = 0; b < 8; b++) oa[p][b] = make_float2(0.f, 0.f);

    #pragma unroll 2
    for (int k = 0; k < HID; k++) {
        float4 w = __ldg((const float4*)(g_Wout_t + k * OUTD + tx * 4));
        float2 w0 = make_float2(w.x, w.y), w1 = make_float2(w.z, w.w);
        #pragma unroll
        for (int b = 0; b < 8; b++) {
            float h = hrow[k * HSTRIDE + b];
            float2 h2 = make_float2(h, h);
            oa[0][b] = ffma2(w0, h2, oa[0][b]);
            oa[1][b] = ffma2(w1, h2, oa[1][b]);
        }
    }
    float4 bo = *(const float4*)(bout + tx * 4);
    #pragma unroll
    for (int b = 0; b < 8; b++) {
        float4 o;
        o.x = oa[0][b].x + bo.x;
        o.y = oa[0][b].y + bo.y;
        o.z = oa[1][b].x + bo.z;
        o.w = oa[1][b].y + bo.w;
        *(float4*)(out + (size_t)(b0 + ty * 8 + b) * OUTD + tx * 4) = o;
    }
}

// ---------------- launch ----------------
extern "C" void kernel_launch(void* const* d_in, const int* in_sizes, int n_in,
                              void* d_out, int out_size) {
    const int*   x     = (const int*)d_in[0];
    const float* embed = (const float*)d_in[1];
    const float* Wih   = (const float*)d_in[2];
    const float* Whh   = (const float*)d_in[3];
    const float* bih   = (const float*)d_in[4];
    const float* bhh   = (const float*)d_in[5];
    const float* Wout  = (const float*)d_in[6];
    const float* bout  = (const float*)d_in[7];
    float* out = (float*)d_out;

    static bool attr_done = false;
    if (!attr_done) {
        cudaFuncSetAttribute(phase2_kernel, cudaFuncAttributeMaxDynamicSharedMemorySize, P2_SMEM);
        attr_done = true;
    }

    prep_kernel<<<(HID * G3 + 255) / 256, 256>>>(Wih, Whh, bih, bhh, Wout);
    table_kernel<<<NVAL, G3>>>(embed);
    phase2_kernel<<<B_SZ / 64, 256, P2_SMEM>>>(x, bhh, bout, out);
}

// round 6
// speedup vs baseline: 1.0472x; 1.0472x over previous
#include <cuda_runtime.h>
#include <cstdint>

#define B_SZ 8192
#define L_SZ 64
#define EMB  64
#define HID  128
#define G3   384
#define OUTD 128
#define NVAL 1000

#define ROWS_CTA 56          // 7 warps x 8 rows
#define NWARPS   7
#define NTHREADS (NWARPS * 32)
#define NCTAS    ((B_SZ + ROWS_CTA - 1) / ROWS_CTA)   // 147

__device__ float g_tab[NVAL * G3];      // [v][gj] xg table (L2-hot, 1.5MB)
__device__ float g_Wih_t[EMB * G3];
__device__ float g_Whh_t[HID * G3];     // [k][gj]
__device__ float g_Wout_t[HID * OUTD];  // [k][o]
__device__ float g_cbias[G3];

__device__ __forceinline__ float2 ffma2(float2 a, float2 b, float2 c) {
    unsigned long long au = *(unsigned long long*)&a, bu = *(unsigned long long*)&b,
                       cu = *(unsigned long long*)&c, du;
    asm("fma.rn.f32x2 %0, %1, %2, %3;" : "=l"(du) : "l"(au), "l"(bu), "l"(cu));
    return *(float2*)&du;
}
__device__ __forceinline__ float fsig(float x) {
    float e, r;
    asm("ex2.approx.f32 %0, %1;" : "=f"(e) : "f"(-1.4426950408889634f * x));
    asm("rcp.approx.f32 %0, %1;" : "=f"(r) : "f"(1.0f + e));
    return r;
}
__device__ __forceinline__ float ftanh(float x) {
    float e, r;
    asm("ex2.approx.f32 %0, %1;" : "=f"(e) : "f"(-2.8853900817779268f * x));
    asm("rcp.approx.f32 %0, %1;" : "=f"(r) : "f"(1.0f + e));
    return fmaf(2.0f, r, -1.0f);
}

__global__ void prep_kernel(const float* __restrict__ Wih, const float* __restrict__ Whh,
                            const float* __restrict__ bih, const float* __restrict__ bhh,
                            const float* __restrict__ Wout) {
    int i = blockIdx.x * blockDim.x + threadIdx.x;
    if (i < EMB * G3) { int k = i / G3, gj = i % G3; g_Wih_t[i] = Wih[gj * EMB + k]; }
    if (i < HID * G3) { int k = i / G3, gj = i % G3; g_Whh_t[i] = Whh[gj * HID + k]; }
    if (i < HID * OUTD) { int k = i / OUTD, o = i % OUTD; g_Wout_t[i] = Wout[o * HID + k]; }
    if (i < G3) g_cbias[i] = bih[i] + (i < 2 * HID ? bhh[i] : 0.0f);
}

__global__ void table_kernel(const float* __restrict__ embed) {
    __shared__ float es[EMB];
    const int v = blockIdx.x, gj = threadIdx.x;
    if (gj < EMB) es[gj] = embed[v * EMB + gj];
    __syncthreads();
    float acc = 0.0f;
    #pragma unroll 8
    for (int k = 0; k < EMB; k++) acc = fmaf(es[k], g_Wih_t[k * G3 + gj], acc);
    g_tab[v * G3 + gj] = acc + g_cbias[gj];
}

// ---------------- phase 2: warp-decoupled GRU + output projection ----------------
#define HSTRIDE 57
#define P2_SMEM (HID * G3 * 4 + HID * HSTRIDE * 4)   // 192KB + 28.5KB = 225792B

__global__ __launch_bounds__(NTHREADS, 1) void phase2_kernel(const int* __restrict__ x,
                                                             const float* __restrict__ bhh,
                                                             const float* __restrict__ bout,
                                                             float* __restrict__ out) {
    extern __shared__ float sm2[];
    float* Ws = sm2;                // [k][gj] 128x384
    float* Hs = sm2 + HID * G3;     // [k][col] 128x57, col = w*8+b (warp-private columns)

    const int tid = threadIdx.x;
    const int tx = tid & 31, w = tid >> 5;
    const int b0 = blockIdx.x * ROWS_CTA;
    const float* __restrict__ tab = g_tab;

    // cooperative stage of Whh_t; zero h
    {
        const float4* src = (const float4*)g_Whh_t;
        float4* dst = (float4*)Ws;
        for (int i = tid; i < HID * G3 / 4; i += NTHREADS) dst[i] = src[i];
    }
    for (int i = tid; i < HID * HSTRIDE; i += NTHREADS) Hs[i] = 0.0f;
    __syncthreads();   // the ONLY block-wide barrier

    if (b0 + w * 8 >= B_SZ) return;   // tail CTA: inactive warps exit

    float4 pbn4 = *(const float4*)(bhh + 256 + tx * 4);
    float2 pbn0 = make_float2(pbn4.x, pbn4.y);
    float2 pbn1 = make_float2(pbn4.z, pbn4.w);

    const float* wrow = Ws + tx * 4;
    const float* hrow = Hs + w * 8;
    const int rowbase = b0 + w * 8;

    float hp[8][4];   // this thread's h slice: rows tx*4+j, cols b (persistent)
    #pragma unroll
    for (int b = 0; b < 8; b++)
        #pragma unroll
        for (int j = 0; j < 4; j++) hp[b][j] = 0.0f;

    for (int t = 0; t < L_SZ; t++) {
        int idx[8];
        #pragma unroll
        for (int b = 0; b < 8; b++)
            idx[b] = x[(size_t)(rowbase + b) * L_SZ + t];

        float2 ar[2][8], az[2][8], an[2][8];
        #pragma unroll
        for (int b = 0; b < 8; b++) {
            const float* trow = tab + (size_t)idx[b] * G3 + tx * 4;
            float4 vr = __ldg((const float4*)(trow));
            float4 vz = __ldg((const float4*)(trow + 128));
            ar[0][b] = make_float2(vr.x, vr.y); ar[1][b] = make_float2(vr.z, vr.w);
            az[0][b] = make_float2(vz.x, vz.y); az[1][b] = make_float2(vz.z, vz.w);
            an[0][b] = pbn0;                    an[1][b] = pbn1;
        }

        #pragma unroll 2
        for (int k = 0; k < HID; k++) {
            float4 wr = *(const float4*)(wrow + k * G3);
            float4 wz = *(const float4*)(wrow + k * G3 + 128);
            float4 wn = *(const float4*)(wrow + k * G3 + 256);
            float2 wr0 = make_float2(wr.x, wr.y), wr1 = make_float2(wr.z, wr.w);
            float2 wz0 = make_float2(wz.x, wz.y), wz1 = make_float2(wz.z, wz.w);
            float2 wn0 = make_float2(wn.x, wn.y), wn1 = make_float2(wn.z, wn.w);
            #pragma unroll
            for (int b = 0; b < 8; b++) {
                float h = hrow[k * HSTRIDE + b];
                float2 h2 = make_float2(h, h);
                ar[0][b] = ffma2(wr0, h2, ar[0][b]);
                ar[1][b] = ffma2(wr1, h2, ar[1][b]);
                az[0][b] = ffma2(wz0, h2, az[0][b]);
                az[1][b] = ffma2(wz1, h2, az[1][b]);
                an[0][b] = ffma2(wn0, h2, an[0][b]);
                an[1][b] = ffma2(wn1, h2, an[1][b]);
            }
        }

        // gate math — h_prev lives in registers (hp), no SMEM re-read
        #pragma unroll
        for (int b = 0; b < 8; b++) {
            float4 xn4 = __ldg((const float4*)(tab + (size_t)idx[b] * G3 + 256 + tx * 4));
            float xn[4] = {xn4.x, xn4.y, xn4.z, xn4.w};
            float rr[4] = {ar[0][b].x, ar[0][b].y, ar[1][b].x, ar[1][b].y};
            float zz[4] = {az[0][b].x, az[0][b].y, az[1][b].x, az[1][b].y};
            float nn[4] = {an[0][b].x, an[0][b].y, an[1][b].x, an[1][b].y};
            #pragma unroll
            for (int j = 0; j < 4; j++) {
                float r = fsig(rr[j]);
                float z = fsig(zz[j]);
                float n = ftanh(fmaf(r, nn[j], xn[j]));
                hp[b][j] = fmaf(z, hp[b][j] - n, n);   // (1-z)*n + z*h
            }
        }
        __syncwarp();   // all lanes done reading old Hs
        #pragma unroll
        for (int b = 0; b < 8; b++)
            #pragma unroll
            for (int j = 0; j < 4; j++)
                Hs[(tx * 4 + j) * HSTRIDE + w * 8 + b] = hp[b][j];
        __syncwarp();   // writes visible to warp before next step's reads
    }

    // output projection (warp-local): out[b][o] = sum_k Hs[k][col] * Wout_t[k][o] + bout[o]
    float2 oa[2][8];
    #pragma unroll
    for (int p = 0; p < 2; p++)
        #pragma unroll
        for (int b = 0; b < 8; b++) oa[p][b] = make_float2(0.f, 0.f);

    #pragma unroll 2
    for (int k = 0; k < HID; k++) {
        float4 ww = __ldg((const float4*)(g_Wout_t + k * OUTD + tx * 4));
        float2 w0 = make_float2(ww.x, ww.y), w1 = make_float2(ww.z, ww.w);
        #pragma unroll
        for (int b = 0; b < 8; b++) {
            float h = hrow[k * HSTRIDE + b];
            float2 h2 = make_float2(h, h);
            oa[0][b] = ffma2(w0, h2, oa[0][b]);
            oa[1][b] = ffma2(w1, h2, oa[1][b]);
        }
    }
    float4 bo = *(const float4*)(bout + tx * 4);
    #pragma unroll
    for (int b = 0; b < 8; b++) {
        float4 o;
        o.x = oa[0][b].x + bo.x;
        o.y = oa[0][b].y + bo.y;
        o.z = oa[1][b].x + bo.z;
        o.w = oa[1][b].y + bo.w;
        *(float4*)(out + (size_t)(rowbase + b) * OUTD + tx * 4) = o;
    }
}

extern "C" void kernel_launch(void* const* d_in, const int* in_sizes, int n_in,
                              void* d_out, int out_size) {
    const int*   x     = (const int*)d_in[0];
    const float* embed = (const float*)d_in[1];
    const float* Wih   = (const float*)d_in[2];
    const float* Whh   = (const float*)d_in[3];
    const float* bih   = (const float*)d_in[4];
    const float* bhh   = (const float*)d_in[5];
    const float* Wout  = (const float*)d_in[6];
    const float* bout  = (const float*)d_in[7];
    float* out = (float*)d_out;

    static bool attr_done = false;
    if (!attr_done) {
        cudaFuncSetAttribute(phase2_kernel, cudaFuncAttributeMaxDynamicSharedMemorySize, P2_SMEM);
        attr_done = true;
    }

    prep_kernel<<<(HID * G3 + 255) / 256, 256>>>(Wih, Whh, bih, bhh, Wout);
    table_kernel<<<NVAL, G3>>>(embed);
    phase2_kernel<<<NCTAS, NTHREADS, P2_SMEM>>>(x, bhh, bout, out);
}

// round 7
// speedup vs baseline: 2.5846x; 2.4681x over previous
#include <cuda_runtime.h>
#include <cuda_fp16.h>
#include <cstdint>

#define B_SZ 8192
#define L_SZ 64
#define EMB  64
#define HID  128
#define G3   384
#define OUTD 128
#define NVAL 1000

__device__ float g_tab[NVAL * G3];      // xg table (fp32, L2-hot)
__device__ float g_Wih_t[EMB * G3];
__device__ float g_cbias[G3];
__device__ uint32_t g_Bf[8 * 8 * 32 * 12];  // Whh fp16 B-fragments, 96KB
__device__ uint32_t g_Of[8 * 32 * 32];      // Wout fp16 B-fragments, 32KB

__device__ __forceinline__ float fsig(float x) {
    float e, r;
    asm("ex2.approx.f32 %0, %1;" : "=f"(e) : "f"(-1.4426950408889634f * x));
    asm("rcp.approx.f32 %0, %1;" : "=f"(r) : "f"(1.0f + e));
    return r;
}
__device__ __forceinline__ float ftanh(float x) {
    float e, r;
    asm("ex2.approx.f32 %0, %1;" : "=f"(e) : "f"(-2.8853900817779268f * x));
    asm("rcp.approx.f32 %0, %1;" : "=f"(r) : "f"(1.0f + e));
    return fmaf(2.0f, r, -1.0f);
}
__device__ __forceinline__ uint32_t packh2(float lo, float hi) {
    __half2 h = __floats2half2_rn(lo, hi);
    return *reinterpret_cast<uint32_t*>(&h);
}
__device__ __forceinline__ void hmma(float* d, const uint32_t* a, uint32_t b0, uint32_t b1) {
    asm volatile("mma.sync.aligned.m16n8k16.row.col.f32.f16.f16.f32 "
        "{%0,%1,%2,%3}, {%4,%5,%6,%7}, {%8,%9}, {%0,%1,%2,%3};"
        : "+f"(d[0]), "+f"(d[1]), "+f"(d[2]), "+f"(d[3])
        : "r"(a[0]), "r"(a[1]), "r"(a[2]), "r"(a[3]), "r"(b0), "r"(b1));
}

// ---------------- prep: tables, biases, fp16 fragment images ----------------
__global__ void prep_kernel(const float* __restrict__ Wih, const float* __restrict__ Whh,
                            const float* __restrict__ bih, const float* __restrict__ bhh,
                            const float* __restrict__ Wout) {
    int i = blockIdx.x * blockDim.x + threadIdx.x;
    if (i < EMB * G3) { int k = i / G3, gj = i % G3; g_Wih_t[i] = Wih[gj * EMB + k]; }
    if (i < G3) g_cbias[i] = bih[i] + (i < 2 * HID ? bhh[i] : 0.0f);
    if (i < G3 * HID) {   // Whh element: gj = i/HID, k = i%HID
        int gj = i / HID, k = i % HID;
        uint16_t hb = __half_as_ushort(__float2half_rn(Whh[i]));
        int gate = gj >> 7, jr = gj & 127;
        int jc = jr >> 4, nt = (jr >> 3) & 1, nl = jr & 7;
        int kc = k >> 4, kk = k & 15;
        int breg = kk >> 3, q = (kk & 7) >> 1, hs = kk & 1;
        int T = nl * 4 + q, f = gate * 2 + nt;
        int u = ((jc * 8 + kc) * 32 + T) * 12 + f * 2 + breg;
        ((uint16_t*)g_Bf)[u * 2 + hs] = hb;
    }
    if (i < OUTD * HID) { // Wout element: o = i/HID, k = i%HID
        int o = i / HID, k = i % HID;
        uint16_t hb = __half_as_ushort(__float2half_rn(Wout[i]));
        int f = o >> 3, nl = o & 7;
        int kc = k >> 4, kk = k & 15;
        int breg = kk >> 3, q = (kk & 7) >> 1, hs = kk & 1;
        int T = nl * 4 + q;
        int u = (kc * 32 + T) * 32 + f * 2 + breg;
        ((uint16_t*)g_Of)[u * 2 + hs] = hb;
    }
}

__global__ void table_kernel(const float* __restrict__ embed) {
    __shared__ float es[EMB];
    const int v = blockIdx.x, gj = threadIdx.x;
    if (gj < EMB) es[gj] = embed[v * EMB + gj];
    __syncthreads();
    float acc = 0.0f;
    #pragma unroll 8
    for (int k = 0; k < EMB; k++) acc = fmaf(es[k], g_Wih_t[k * G3 + gj], acc);
    g_tab[v * G3 + gj] = acc + g_cbias[gj];
}

// ---------------- GRU: mma.sync fp16, A-from-D register recycling ----------------
#define GRU_SMEM 131072
__global__ __launch_bounds__(128, 1) void gru_kernel(const int* __restrict__ x,
                                                     const float* __restrict__ bhh,
                                                     const float* __restrict__ bout,
                                                     float* __restrict__ out) {
    extern __shared__ uint32_t sm[];
    uint32_t* Bs = sm;            // 24576 u32
    uint32_t* Os = sm + 24576;    // 8192 u32
    const int tid = threadIdx.x;
    {
        uint4* d = (uint4*)sm;
        const uint4* s1 = (const uint4*)g_Bf;
        for (int i = tid; i < 6144; i += 128) d[i] = s1[i];
        const uint4* s2 = (const uint4*)g_Of;
        for (int i = tid; i < 2048; i += 128) d[6144 + i] = s2[i];
    }
    __syncthreads();

    const int w = tid >> 5, T = tid & 31;
    const int g = T >> 2, q2 = (T & 3) * 2;
    const int rowA = blockIdx.x * 64 + w * 16 + g;
    const int rowB = rowA + 8;
    const float* __restrict__ tab = g_tab;

    uint32_t A[32], An[32];
    float hp[64];
    #pragma unroll
    for (int i = 0; i < 32; i++) A[i] = 0u;
    #pragma unroll
    for (int i = 0; i < 64; i++) hp[i] = 0.0f;

    int idxA = x[rowA * L_SZ], idxB = x[rowB * L_SZ];

    #pragma unroll 1
    for (int t = 0; t < L_SZ; t++) {
        const float* tA = tab + (size_t)idxA * G3;
        const float* tB = tab + (size_t)idxB * G3;
        if (t + 1 < L_SZ) {  // prefetch next idx
            idxA = x[rowA * L_SZ + t + 1];
            idxB = x[rowB * L_SZ + t + 1];
        }
        #pragma unroll
        for (int jc = 0; jc < 8; jc++) {
            const int jb = jc * 16 + q2;
            // gather xg slices (L2) + n-gate hidden bias
            float2 xrA0 = *(const float2*)(tA + jb);
            float2 xrA1 = *(const float2*)(tA + jb + 8);
            float2 xrB0 = *(const float2*)(tB + jb);
            float2 xrB1 = *(const float2*)(tB + jb + 8);
            float2 xzA0 = *(const float2*)(tA + 128 + jb);
            float2 xzA1 = *(const float2*)(tA + 128 + jb + 8);
            float2 xzB0 = *(const float2*)(tB + 128 + jb);
            float2 xzB1 = *(const float2*)(tB + 128 + jb + 8);
            float2 xnA0 = *(const float2*)(tA + 256 + jb);
            float2 xnA1 = *(const float2*)(tA + 256 + jb + 8);
            float2 xnB0 = *(const float2*)(tB + 256 + jb);
            float2 xnB1 = *(const float2*)(tB + 256 + jb + 8);
            float2 bn0  = *(const float2*)(bhh + 256 + jb);
            float2 bn1  = *(const float2*)(bhh + 256 + jb + 8);

            float d[6][4];
            #pragma unroll
            for (int f = 0; f < 6; f++)
                #pragma unroll
                for (int p = 0; p < 4; p++) d[f][p] = 0.0f;

            #pragma unroll
            for (int kc = 0; kc < 8; kc++) {
                const uint4* bp = (const uint4*)(Bs + ((jc * 8 + kc) * 32 + T) * 12);
                uint4 b0 = bp[0], b1 = bp[1], b2 = bp[2];
                hmma(d[0], &A[kc * 4], b0.x, b0.y);
                hmma(d[1], &A[kc * 4], b0.z, b0.w);
                hmma(d[2], &A[kc * 4], b1.x, b1.y);
                hmma(d[3], &A[kc * 4], b1.z, b1.w);
                hmma(d[4], &A[kc * 4], b2.x, b2.y);
                hmma(d[5], &A[kc * 4], b2.z, b2.w);
            }

            // epilogue: u = nt*4 + pos; pos = {(g,j0),(g,j0+1),(g+8,j0),(g+8,j0+1)}
            float xr[8] = {xrA0.x, xrA0.y, xrB0.x, xrB0.y, xrA1.x, xrA1.y, xrB1.x, xrB1.y};
            float xz[8] = {xzA0.x, xzA0.y, xzB0.x, xzB0.y, xzA1.x, xzA1.y, xzB1.x, xzB1.y};
            float xn[8] = {xnA0.x, xnA0.y, xnB0.x, xnB0.y, xnA1.x, xnA1.y, xnB1.x, xnB1.y};
            float bn[8] = {bn0.x, bn0.y, bn0.x, bn0.y, bn1.x, bn1.y, bn1.x, bn1.y};
            float hv[8];
            #pragma unroll
            for (int u = 0; u < 8; u++) {
                int nt = u >> 2, pos = u & 3;
                float r = fsig(d[nt][pos] + xr[u]);
                float z = fsig(d[2 + nt][pos] + xz[u]);
                float n = ftanh(fmaf(r, d[4 + nt][pos] + bn[u], xn[u]));
                float h = fmaf(z, hp[jc * 8 + u] - n, n);
                hp[jc * 8 + u] = h;
                hv[u] = h;
            }
            // D-layout -> next step's A-fragment for k-chunk jc
            An[jc * 4 + 0] = packh2(hv[0], hv[1]);
            An[jc * 4 + 1] = packh2(hv[2], hv[3]);
            An[jc * 4 + 2] = packh2(hv[4], hv[5]);
            An[jc * 4 + 3] = packh2(hv[6], hv[7]);
        }
        #pragma unroll
        for (int i = 0; i < 32; i++) A[i] = An[i];
    }

    // output projection: out = h @ Wout^T + bout (fp16 mma, fp32 accum)
    float od[16][4];
    #pragma unroll
    for (int f = 0; f < 16; f++)
        #pragma unroll
        for (int p = 0; p < 4; p++) od[f][p] = 0.0f;
    #pragma unroll
    for (int kc = 0; kc < 8; kc++) {
        const uint4* op = (const uint4*)(Os + (kc * 32 + T) * 32);
        #pragma unroll
        for (int f2 = 0; f2 < 8; f2++) {
            uint4 v = op[f2];
            hmma(od[f2 * 2 + 0], &A[kc * 4], v.x, v.y);
            hmma(od[f2 * 2 + 1], &A[kc * 4], v.z, v.w);
        }
    }
    #pragma unroll
    for (int f = 0; f < 16; f++) {
        float2 bo = *(const float2*)(bout + f * 8 + q2);
        float2 oA = make_float2(od[f][0] + bo.x, od[f][1] + bo.y);
        float2 oB = make_float2(od[f][2] + bo.x, od[f][3] + bo.y);
        *(float2*)(out + (size_t)rowA * OUTD + f * 8 + q2) = oA;
        *(float2*)(out + (size_t)rowB * OUTD + f * 8 + q2) = oB;
    }
}

extern "C" void kernel_launch(void* const* d_in, const int* in_sizes, int n_in,
                              void* d_out, int out_size) {
    const int*   x     = (const int*)d_in[0];
    const float* embed = (const float*)d_in[1];
    const float* Wih   = (const float*)d_in[2];
    const float* Whh   = (const float*)d_in[3];
    const float* bih   = (const float*)d_in[4];
    const float* bhh   = (const float*)d_in[5];
    const float* Wout  = (const float*)d_in[6];
    const float* bout  = (const float*)d_in[7];
    float* out = (float*)d_out;

    static bool attr_done = false;
    if (!attr_done) {
        cudaFuncSetAttribute(gru_kernel, cudaFuncAttributeMaxDynamicSharedMemorySize, GRU_SMEM);
        attr_done = true;
    }

    prep_kernel<<<192, 256>>>(Wih, Whh, bih, bhh, Wout);
    table_kernel<<<NVAL, G3>>>(embed);
    gru_kernel<<<B_SZ / 64, 128, GRU_SMEM>>>(x, bhh, bout, out);
}

// round 8
// speedup vs baseline: 3.8205x; 1.4782x over previous
#include <cuda_runtime.h>
#include <cuda_fp16.h>
#include <cstdint>

#define B_SZ 8192
#define L_SZ 64
#define EMB  64
#define HID  128
#define G3   384
#define OUTD 128
#define NVAL 1000

__device__ float g_tab[NVAL * G3];      // xg table, PERMUTED within 16-chunks (fp32, L2-hot)
__device__ float g_Wih_t[EMB * G3];
__device__ float g_cbias[G3];
__device__ uint32_t g_Bf[8 * 8 * 32 * 12];  // Whh fp16 B-fragments, 96KB
__device__ uint32_t g_Of[8 * 32 * 32];      // Wout fp16 B-fragments, 32KB

__device__ __forceinline__ float ftanh_fast(float x) {
    float r;
    asm("tanh.approx.f32 %0, %1;" : "=f"(r) : "f"(x));
    return r;
}
__device__ __forceinline__ float fsig_fast(float x) {
    return fmaf(0.5f, ftanh_fast(0.5f * x), 0.5f);
}
__device__ __forceinline__ float ftanh(float x) {   // accurate, for n gate
    float e, r;
    asm("ex2.approx.f32 %0, %1;" : "=f"(e) : "f"(-2.8853900817779268f * x));
    asm("rcp.approx.f32 %0, %1;" : "=f"(r) : "f"(1.0f + e));
    return fmaf(2.0f, r, -1.0f);
}
__device__ __forceinline__ uint32_t packh2(float lo, float hi) {
    __half2 h = __floats2half2_rn(lo, hi);
    return *reinterpret_cast<uint32_t*>(&h);
}
__device__ __forceinline__ void hmma(float* d, const uint32_t* a, uint32_t b0, uint32_t b1) {
    asm volatile("mma.sync.aligned.m16n8k16.row.col.f32.f16.f16.f32 "
        "{%0,%1,%2,%3}, {%4,%5,%6,%7}, {%8,%9}, {%0,%1,%2,%3};"
        : "+f"(d[0]), "+f"(d[1]), "+f"(d[2]), "+f"(d[3])
        : "r"(a[0]), "r"(a[1]), "r"(a[2]), "r"(a[3]), "r"(b0), "r"(b1));
}
// permuted position within a 16-chunk: thread quad a reads floats {2a,2a+1,2a+8,2a+9} as one float4
__device__ __forceinline__ int pperm(int o) {
    return 4 * ((o & 7) >> 1) + (((o >> 3) & 1) << 1) + (o & 1);
}

// ---------------- prep: fragment images ----------------
__global__ void prep_kernel(const float* __restrict__ Wih, const float* __restrict__ Whh,
                            const float* __restrict__ bih, const float* __restrict__ bhh,
                            const float* __restrict__ Wout) {
    int i = blockIdx.x * blockDim.x + threadIdx.x;
    if (i < EMB * G3) { int k = i / G3, gj = i % G3; g_Wih_t[i] = Wih[gj * EMB + k]; }
    if (i < G3) g_cbias[i] = bih[i] + (i < 2 * HID ? bhh[i] : 0.0f);
    if (i < G3 * HID) {   // Whh element: gj = i/HID, k = i%HID
        int gj = i / HID, k = i % HID;
        uint16_t hb = __half_as_ushort(__float2half_rn(Whh[i]));
        int gate = gj >> 7, jr = gj & 127;
        int jc = jr >> 4, nt = (jr >> 3) & 1, nl = jr & 7;
        int kc = k >> 4, kk = k & 15;
        int breg = kk >> 3, q = (kk & 7) >> 1, hs = kk & 1;
        int T = nl * 4 + q, f = gate * 2 + nt;
        int u = ((jc * 8 + kc) * 32 + T) * 12 + f * 2 + breg;
        ((uint16_t*)g_Bf)[u * 2 + hs] = hb;
    }
    if (i < OUTD * HID) { // Wout element: o = i/HID, k = i%HID
        int o = i / HID, k = i % HID;
        uint16_t hb = __half_as_ushort(__float2half_rn(Wout[i]));
        int f = o >> 3, nl = o & 7;
        int kc = k >> 4, kk = k & 15;
        int breg = kk >> 3, q = (kk & 7) >> 1, hs = kk & 1;
        int T = nl * 4 + q;
        int u = (kc * 32 + T) * 32 + f * 2 + breg;
        ((uint16_t*)g_Of)[u * 2 + hs] = hb;
    }
}

// table with permuted chunk layout
__global__ void table_kernel(const float* __restrict__ embed) {
    __shared__ float es[EMB];
    const int v = blockIdx.x, gj = threadIdx.x;
    if (gj < EMB) es[gj] = embed[v * EMB + gj];
    __syncthreads();
    float acc = 0.0f;
    #pragma unroll 8
    for (int k = 0; k < EMB; k++) acc = fmaf(es[k], g_Wih_t[k * G3 + gj], acc);
    const int gate = gj >> 7, rest = gj & 127, chunk = rest >> 4, o = rest & 15;
    g_tab[v * G3 + gate * 128 + chunk * 16 + pperm(o)] = acc + g_cbias[gj];
}

// ---------------- GRU: mma.sync fp16, A-from-D recycling, permuted float4 xg loads ----------------
#define GRU_SMEM (131072 + 512)
__global__ __launch_bounds__(128, 1) void gru_kernel(const int* __restrict__ x,
                                                     const float* __restrict__ bhh,
                                                     const float* __restrict__ bout,
                                                     float* __restrict__ out) {
    extern __shared__ uint32_t sm[];
    uint32_t* Bs = sm;                      // 24576 u32
    uint32_t* Os = sm + 24576;              // 8192 u32
    float* bns = (float*)(sm + 32768);      // 128 floats, permuted bhh_n
    const int tid = threadIdx.x;
    {
        uint4* d = (uint4*)sm;
        const uint4* s1 = (const uint4*)g_Bf;
        for (int i = tid; i < 6144; i += 128) d[i] = s1[i];
        const uint4* s2 = (const uint4*)g_Of;
        for (int i = tid; i < 2048; i += 128) d[6144 + i] = s2[i];
    }
    if (tid < 128) {
        int o = tid & 15, chunk = tid >> 4;
        bns[chunk * 16 + pperm(o)] = bhh[256 + tid];
    }
    __syncthreads();

    const int w = tid >> 5, T = tid & 31;
    const int g = T >> 2, a4 = (T & 3) * 4;
    const int rowA = blockIdx.x * 64 + w * 16 + g;
    const int rowB = rowA + 8;
    const float* __restrict__ tab = g_tab;

    uint32_t A[32], An[32];
    float hp[64];
    #pragma unroll
    for (int i = 0; i < 32; i++) A[i] = 0u;
    #pragma unroll
    for (int i = 0; i < 64; i++) hp[i] = 0.0f;

    int idxA = x[rowA * L_SZ], idxB = x[rowB * L_SZ];

    #pragma unroll 1
    for (int t = 0; t < L_SZ; t++) {
        const float* tA = tab + (size_t)idxA * G3 + a4;
        const float* tB = tab + (size_t)idxB * G3 + a4;
        if (t + 1 < L_SZ) {
            idxA = x[rowA * L_SZ + t + 1];
            idxB = x[rowB * L_SZ + t + 1];
        }
        #pragma unroll
        for (int jc = 0; jc < 8; jc++) {
            const int jo = jc * 16;
            // permuted loads: one float4 per (gate,row) = {j:q2, q2+1, q2+8, q2+9}
            float4 vrA = __ldg((const float4*)(tA + jo));
            float4 vrB = __ldg((const float4*)(tB + jo));
            float4 vzA = __ldg((const float4*)(tA + 128 + jo));
            float4 vzB = __ldg((const float4*)(tB + 128 + jo));
            float4 vnA = __ldg((const float4*)(tA + 256 + jo));
            float4 vnB = __ldg((const float4*)(tB + 256 + jo));
            float4 bn4 = *(const float4*)(bns + jo + a4);

            float d[6][4];
            #pragma unroll
            for (int f = 0; f < 6; f++)
                #pragma unroll
                for (int p = 0; p < 4; p++) d[f][p] = 0.0f;

            #pragma unroll
            for (int kc = 0; kc < 8; kc++) {
                const uint4* bp = (const uint4*)(Bs + ((jc * 8 + kc) * 32 + T) * 12);
                uint4 b0 = bp[0], b1 = bp[1], b2 = bp[2];
                hmma(d[0], &A[kc * 4], b0.x, b0.y);
                hmma(d[1], &A[kc * 4], b0.z, b0.w);
                hmma(d[2], &A[kc * 4], b1.x, b1.y);
                hmma(d[3], &A[kc * 4], b1.z, b1.w);
                hmma(d[4], &A[kc * 4], b2.x, b2.y);
                hmma(d[5], &A[kc * 4], b2.z, b2.w);
            }

            // epilogue: u = nt*4 + pos; pos = {(rowA,j0),(rowA,j0+1),(rowB,j0),(rowB,j0+1)}
            float xr[8] = {vrA.x, vrA.y, vrB.x, vrB.y, vrA.z, vrA.w, vrB.z, vrB.w};
            float xz[8] = {vzA.x, vzA.y, vzB.x, vzB.y, vzA.z, vzA.w, vzB.z, vzB.w};
            float xn[8] = {vnA.x, vnA.y, vnB.x, vnB.y, vnA.z, vnA.w, vnB.z, vnB.w};
            float bn[8] = {bn4.x, bn4.y, bn4.x, bn4.y, bn4.z, bn4.w, bn4.z, bn4.w};
            float hv[8];
            #pragma unroll
            for (int u = 0; u < 8; u++) {
                int nt = u >> 2, pos = u & 3;
                float r = fsig_fast(d[nt][pos] + xr[u]);
                float z = fsig_fast(d[2 + nt][pos] + xz[u]);
                float n = ftanh(fmaf(r, d[4 + nt][pos] + bn[u], xn[u]));
                float h = fmaf(z, hp[jc * 8 + u] - n, n);
                hp[jc * 8 + u] = h;
                hv[u] = h;
            }
            An[jc * 4 + 0] = packh2(hv[0], hv[1]);
            An[jc * 4 + 1] = packh2(hv[2], hv[3]);
            An[jc * 4 + 2] = packh2(hv[4], hv[5]);
            An[jc * 4 + 3] = packh2(hv[6], hv[7]);
        }
        #pragma unroll
        for (int i = 0; i < 32; i++) A[i] = An[i];
    }

    // output projection: out = h @ Wout^T + bout
    float od[16][4];
    #pragma unroll
    for (int f = 0; f < 16; f++)
        #pragma unroll
        for (int p = 0; p < 4; p++) od[f][p] = 0.0f;
    #pragma unroll
    for (int kc = 0; kc < 8; kc++) {
        const uint4* op = (const uint4*)(Os + (kc * 32 + T) * 32);
        #pragma unroll
        for (int f2 = 0; f2 < 8; f2++) {
            uint4 v = op[f2];
            hmma(od[f2 * 2 + 0], &A[kc * 4], v.x, v.y);
            hmma(od[f2 * 2 + 1], &A[kc * 4], v.z, v.w);
        }
    }
    const int q2 = (T & 3) * 2;
    #pragma unroll
    for (int f = 0; f < 16; f++) {
        float2 bo = *(const float2*)(bout + f * 8 + q2);
        float2 oA = make_float2(od[f][0] + bo.x, od[f][1] + bo.y);
        float2 oB = make_float2(od[f][2] + bo.x, od[f][3] + bo.y);
        *(float2*)(out + (size_t)rowA * OUTD + f * 8 + q2) = oA;
        *(float2*)(out + (size_t)rowB * OUTD + f * 8 + q2) = oB;
    }
}

extern "C" void kernel_launch(void* const* d_in, const int* in_sizes, int n_in,
                              void* d_out, int out_size) {
    const int*   x     = (const int*)d_in[0];
    const float* embed = (const float*)d_in[1];
    const float* Wih   = (const float*)d_in[2];
    const float* Whh   = (const float*)d_in[3];
    const float* bih   = (const float*)d_in[4];
    const float* bhh   = (const float*)d_in[5];
    const float* Wout  = (const float*)d_in[6];
    const float* bout  = (const float*)d_in[7];
    float* out = (float*)d_out;

    static bool attr_done = false;
    if (!attr_done) {
        cudaFuncSetAttribute(gru_kernel, cudaFuncAttributeMaxDynamicSharedMemorySize, GRU_SMEM);
        attr_done = true;
    }

    prep_kernel<<<192, 256>>>(Wih, Whh, bih, bhh, Wout);
    table_kernel<<<NVAL, G3>>>(embed);
    gru_kernel<<<B_SZ / 64, 128, GRU_SMEM>>>(x, bhh, bout, out);
}